// round 1
// baseline (speedup 1.0000x reference)
#include <cuda_runtime.h>

#define NX 256
#define NY 256
#define NZ 256
#define DETU 128
#define DETV 128
#define NVIEWS 8
#define NSTEPS 192

// Scratch volume for updated = x + reco (allocation-free rule -> __device__ global)
__device__ float g_vol[NX * NY * NZ];

// ---------------------------------------------------------------------------
// Kernel A: updated = x + reco  ->  g_vol (scratch) and relu(updated) -> out
// ---------------------------------------------------------------------------
__global__ void add_relu_kernel(const float* __restrict__ x,
                                const float* __restrict__ r,
                                float* __restrict__ relu_out) {
    int i = blockIdx.x * blockDim.x + threadIdx.x;
    const float4* x4 = (const float4*)x;
    const float4* r4 = (const float4*)r;
    float4 a = x4[i];
    float4 b = r4[i];
    float4 s;
    s.x = a.x + b.x; s.y = a.y + b.y; s.z = a.z + b.z; s.w = a.w + b.w;
    ((float4*)g_vol)[i] = s;
    float4 rl;
    rl.x = fmaxf(s.x, 0.0f); rl.y = fmaxf(s.y, 0.0f);
    rl.z = fmaxf(s.z, 0.0f); rl.w = fmaxf(s.w, 0.0f);
    ((float4*)relu_out)[i] = rl;
}

// ---------------------------------------------------------------------------
// Trilinear sample with zero-outside semantics (matches reference masking)
// ---------------------------------------------------------------------------
__device__ __forceinline__ float trilin(float px, float py, float pz) {
    float xf = floorf(px), yf = floorf(py), zf = floorf(pz);
    float fx = px - xf, fy = py - yf, fz = pz - zf;
    int x0 = (int)xf, y0 = (int)yf, z0 = (int)zf;
    int x1 = x0 + 1, y1 = y0 + 1, z1 = z0 + 1;

    bool bx0 = ((unsigned)x0 < (unsigned)NX);
    bool bx1 = ((unsigned)x1 < (unsigned)NX);
    bool by0 = ((unsigned)y0 < (unsigned)NY);
    bool by1 = ((unsigned)y1 < (unsigned)NY);
    bool bz0 = ((unsigned)z0 < (unsigned)NZ);
    bool bz1 = ((unsigned)z1 < (unsigned)NZ);

    int cx0 = min(max(x0, 0), NX - 1), cx1 = min(max(x1, 0), NX - 1);
    int cy0 = min(max(y0, 0), NY - 1), cy1 = min(max(y1, 0), NY - 1);
    int cz0 = min(max(z0, 0), NZ - 1), cz1 = min(max(z1, 0), NZ - 1);

    int bx0i = cx0 * (NY * NZ), bx1i = cx1 * (NY * NZ);
    int oy0 = cy0 * NZ, oy1 = cy1 * NZ;

    float v000 = (bx0 & by0 & bz0) ? __ldg(&g_vol[bx0i + oy0 + cz0]) : 0.0f;
    float v001 = (bx0 & by0 & bz1) ? __ldg(&g_vol[bx0i + oy0 + cz1]) : 0.0f;
    float v010 = (bx0 & by1 & bz0) ? __ldg(&g_vol[bx0i + oy1 + cz0]) : 0.0f;
    float v011 = (bx0 & by1 & bz1) ? __ldg(&g_vol[bx0i + oy1 + cz1]) : 0.0f;
    float v100 = (bx1 & by0 & bz0) ? __ldg(&g_vol[bx1i + oy0 + cz0]) : 0.0f;
    float v101 = (bx1 & by0 & bz1) ? __ldg(&g_vol[bx1i + oy0 + cz1]) : 0.0f;
    float v110 = (bx1 & by1 & bz0) ? __ldg(&g_vol[bx1i + oy1 + cz0]) : 0.0f;
    float v111 = (bx1 & by1 & bz1) ? __ldg(&g_vol[bx1i + oy1 + cz1]) : 0.0f;

    float gz = 1.0f - fz, gy = 1.0f - fy, gx = 1.0f - fx;
    float c00 = v000 * gz + v001 * fz;
    float c01 = v010 * gz + v011 * fz;
    float c10 = v100 * gz + v101 * fz;
    float c11 = v110 * gz + v111 * fz;
    float c0 = c00 * gy + c01 * fy;
    float c1 = c10 * gy + c11 * fy;
    return c0 * gx + c1 * fx;
}

// ---------------------------------------------------------------------------
// Kernel B: cone-beam forward projection with slab-clipped ray marching
// ---------------------------------------------------------------------------
__global__ void proj_kernel(const float* __restrict__ src_pos,
                            const float* __restrict__ det_center,
                            const float* __restrict__ det_u_vec,
                            const float* __restrict__ det_v_vec,
                            const float* __restrict__ pdu,
                            const float* __restrict__ pdv,
                            const float* __restrict__ psp,
                            float* __restrict__ sino) {
    const int v = threadIdx.x;      // detector v (z axis) — contiguous output + z locality
    const int u = blockIdx.x;       // detector u
    const int view = blockIdx.y;    // view

    const float du = __ldg(pdu);
    const float dv = __ldg(pdv);
    const float sp = __ldg(psp);
    const float inv_sp = 1.0f / sp;

    const float sx = __ldg(&src_pos[view * 3 + 0]);
    const float sy = __ldg(&src_pos[view * 3 + 1]);
    const float sz = __ldg(&src_pos[view * 3 + 2]);
    const float ccx = __ldg(&det_center[view * 3 + 0]);
    const float ccy = __ldg(&det_center[view * 3 + 1]);
    const float ccz = __ldg(&det_center[view * 3 + 2]);
    const float ux = __ldg(&det_u_vec[view * 3 + 0]);
    const float uy = __ldg(&det_u_vec[view * 3 + 1]);
    const float uz = __ldg(&det_u_vec[view * 3 + 2]);
    const float vx = __ldg(&det_v_vec[view * 3 + 0]);
    const float vy = __ldg(&det_v_vec[view * 3 + 1]);
    const float vz = __ldg(&det_v_vec[view * 3 + 2]);

    const float uu = ((float)u - (float)(DETU - 1) * 0.5f) * du;
    const float vv = ((float)v - (float)(DETV - 1) * 0.5f) * dv;

    // detector point and ray diff (world coords)
    const float dpx = ccx + uu * ux + vv * vx;
    const float dpy = ccy + uu * uy + vv * vy;
    const float dpz = ccz + uu * uz + vv * vz;
    const float dx = dpx - sx;
    const float dy = dpy - sy;
    const float dz = dpz - sz;
    const float ray_len = sqrtf(dx * dx + dy * dy + dz * dz);

    // voxel-space line for slab clipping: q(s) = p0 + s*d
    const float p0x = sx * inv_sp + (float)(NX - 1) * 0.5f;
    const float p0y = sy * inv_sp + (float)(NY - 1) * 0.5f;
    const float p0z = sz * inv_sp + (float)(NZ - 1) * 0.5f;
    const float ddx = dx * inv_sp;
    const float ddy = dy * inv_sp;
    const float ddz = dz * inv_sp;

    float t0 = 0.0f, t1 = 1.0f;
    // Any sample with coordinate outside (-1, N) in some dim contributes exactly 0.
    {
        if (fabsf(ddx) > 1e-12f) {
            float ta = (-1.0f - p0x) / ddx, tb = ((float)NX - p0x) / ddx;
            t0 = fmaxf(t0, fminf(ta, tb)); t1 = fminf(t1, fmaxf(ta, tb));
        } else if (p0x <= -1.0f || p0x >= (float)NX) { t1 = -1.0f; }
        if (fabsf(ddy) > 1e-12f) {
            float ta = (-1.0f - p0y) / ddy, tb = ((float)NY - p0y) / ddy;
            t0 = fmaxf(t0, fminf(ta, tb)); t1 = fminf(t1, fmaxf(ta, tb));
        } else if (p0y <= -1.0f || p0y >= (float)NY) { t1 = -1.0f; }
        if (fabsf(ddz) > 1e-12f) {
            float ta = (-1.0f - p0z) / ddz, tb = ((float)NZ - p0z) / ddz;
            t0 = fmaxf(t0, fminf(ta, tb)); t1 = fminf(t1, fmaxf(ta, tb));
        } else if (p0z <= -1.0f || p0z >= (float)NZ) { t1 = -1.0f; }
    }

    const float inv_n = 1.0f / (float)NSTEPS;
    int k0 = 0, k1 = -1;
    if (t1 > t0) {
        // slightly conservative bounds (never drop a possibly-nonzero step)
        k0 = (int)ceilf(t0 * (float)NSTEPS - 0.5f) - 1;
        k1 = (int)floorf(t1 * (float)NSTEPS - 0.5f) + 1;
        k0 = max(k0, 0);
        k1 = min(k1, NSTEPS - 1);
    }

    const float cx = (float)(NX - 1) * 0.5f;
    const float cy = (float)(NY - 1) * 0.5f;
    const float cz = (float)(NZ - 1) * 0.5f;

    float acc = 0.0f;
#pragma unroll 2
    for (int k = k0; k <= k1; ++k) {
        float s = ((float)k + 0.5f) * inv_n;
        // mirror reference arithmetic: (src + s*diff)/spacing + center
        float wxp = fmaf(s, dx, sx) * inv_sp + cx;
        float wyp = fmaf(s, dy, sy) * inv_sp + cy;
        float wzp = fmaf(s, dz, sz) * inv_sp + cz;
        acc += trilin(wxp, wyp, wzp);
    }

    sino[(view * DETU + u) * DETV + v] = acc * (ray_len * inv_n);
}

// ---------------------------------------------------------------------------
// Launch
// ---------------------------------------------------------------------------
extern "C" void kernel_launch(void* const* d_in, const int* in_sizes, int n_in,
                              void* d_out, int out_size) {
    const float* x    = (const float*)d_in[0];
    const float* reco = (const float*)d_in[1];
    const float* src  = (const float*)d_in[2];
    const float* dc   = (const float*)d_in[3];
    const float* duv  = (const float*)d_in[4];
    const float* dvv  = (const float*)d_in[5];
    const float* pdu  = (const float*)d_in[6];
    const float* pdv  = (const float*)d_in[7];
    const float* psp  = (const float*)d_in[8];

    float* out  = (float*)d_out;
    float* sino = out;                                   // [8,128,128]
    float* relu = out + NVIEWS * DETU * DETV;            // [256^3]

    const int n4 = (NX * NY * NZ) / 4;
    add_relu_kernel<<<n4 / 256, 256>>>(x, reco, relu);

    dim3 grid(DETU, NVIEWS);
    proj_kernel<<<grid, DETV>>>(src, dc, duv, dvv, pdu, pdv, psp, sino);
}

// round 2
// speedup vs baseline: 1.0984x; 1.0984x over previous
#include <cuda_runtime.h>

#define NX 256
#define NY 256
#define NZ 256
#define DETU 128
#define DETV 128
#define NVIEWS 8
#define NSTEPS 192

// Scratch volume for updated = x + reco (allocation-free rule -> __device__ global)
__device__ float g_vol[NX * NY * NZ];

// ---------------------------------------------------------------------------
// Kernel A: updated = x + reco  ->  g_vol (scratch) and relu(updated) -> out
// (HBM-roofline bound: 256 MB @ ~7.2 TB/s; leave as-is)
// ---------------------------------------------------------------------------
__global__ void add_relu_kernel(const float* __restrict__ x,
                                const float* __restrict__ r,
                                float* __restrict__ relu_out) {
    int i = blockIdx.x * blockDim.x + threadIdx.x;
    const float4* x4 = (const float4*)x;
    const float4* r4 = (const float4*)r;
    float4 a = x4[i];
    float4 b = r4[i];
    float4 s;
    s.x = a.x + b.x; s.y = a.y + b.y; s.z = a.z + b.z; s.w = a.w + b.w;
    ((float4*)g_vol)[i] = s;
    float4 rl;
    rl.x = fmaxf(s.x, 0.0f); rl.y = fmaxf(s.y, 0.0f);
    rl.z = fmaxf(s.z, 0.0f); rl.w = fmaxf(s.w, 0.0f);
    ((float4*)relu_out)[i] = rl;
}

// ---------------------------------------------------------------------------
// Masked trilinear sample (boundary steps only): zero-outside semantics
// ---------------------------------------------------------------------------
__device__ __forceinline__ float trilin_masked(float px, float py, float pz) {
    float xf = floorf(px), yf = floorf(py), zf = floorf(pz);
    float fx = px - xf, fy = py - yf, fz = pz - zf;
    int x0 = (int)xf, y0 = (int)yf, z0 = (int)zf;
    int x1 = x0 + 1, y1 = y0 + 1, z1 = z0 + 1;

    bool bx0 = ((unsigned)x0 < (unsigned)NX);
    bool bx1 = ((unsigned)x1 < (unsigned)NX);
    bool by0 = ((unsigned)y0 < (unsigned)NY);
    bool by1 = ((unsigned)y1 < (unsigned)NY);
    bool bz0 = ((unsigned)z0 < (unsigned)NZ);
    bool bz1 = ((unsigned)z1 < (unsigned)NZ);

    int cx0 = min(max(x0, 0), NX - 1), cx1 = min(max(x1, 0), NX - 1);
    int cy0 = min(max(y0, 0), NY - 1), cy1 = min(max(y1, 0), NY - 1);
    int cz0 = min(max(z0, 0), NZ - 1), cz1 = min(max(z1, 0), NZ - 1);

    int bx0i = cx0 * (NY * NZ), bx1i = cx1 * (NY * NZ);
    int oy0 = cy0 * NZ, oy1 = cy1 * NZ;

    float v000 = (bx0 & by0 & bz0) ? __ldg(&g_vol[bx0i + oy0 + cz0]) : 0.0f;
    float v001 = (bx0 & by0 & bz1) ? __ldg(&g_vol[bx0i + oy0 + cz1]) : 0.0f;
    float v010 = (bx0 & by1 & bz0) ? __ldg(&g_vol[bx0i + oy1 + cz0]) : 0.0f;
    float v011 = (bx0 & by1 & bz1) ? __ldg(&g_vol[bx0i + oy1 + cz1]) : 0.0f;
    float v100 = (bx1 & by0 & bz0) ? __ldg(&g_vol[bx1i + oy0 + cz0]) : 0.0f;
    float v101 = (bx1 & by0 & bz1) ? __ldg(&g_vol[bx1i + oy0 + cz1]) : 0.0f;
    float v110 = (bx1 & by1 & bz0) ? __ldg(&g_vol[bx1i + oy1 + cz0]) : 0.0f;
    float v111 = (bx1 & by1 & bz1) ? __ldg(&g_vol[bx1i + oy1 + cz1]) : 0.0f;

    float gz = 1.0f - fz, gy = 1.0f - fy, gx = 1.0f - fx;
    float c00 = v000 * gz + v001 * fz;
    float c01 = v010 * gz + v011 * fz;
    float c10 = v100 * gz + v101 * fz;
    float c11 = v110 * gz + v111 * fz;
    float c0 = c00 * gy + c01 * fy;
    float c1 = c10 * gy + c11 * fy;
    return c0 * gx + c1 * fx;
}

// Fast interior sample: all 8 taps guaranteed in-bounds, no predication
__device__ __forceinline__ float trilin_fast(float px, float py, float pz) {
    float xf = floorf(px), yf = floorf(py), zf = floorf(pz);
    float fx = px - xf, fy = py - yf, fz = pz - zf;
    int x0 = (int)xf, y0 = (int)yf, z0 = (int)zf;

    const float* p = g_vol + ((x0 * NY + y0) * NZ + z0);
    float v000 = __ldg(p);
    float v001 = __ldg(p + 1);
    float v010 = __ldg(p + NZ);
    float v011 = __ldg(p + NZ + 1);
    float v100 = __ldg(p + NY * NZ);
    float v101 = __ldg(p + NY * NZ + 1);
    float v110 = __ldg(p + NY * NZ + NZ);
    float v111 = __ldg(p + NY * NZ + NZ + 1);

    float gz = 1.0f - fz, gy = 1.0f - fy, gx = 1.0f - fx;
    float c00 = v000 * gz + v001 * fz;
    float c01 = v010 * gz + v011 * fz;
    float c10 = v100 * gz + v101 * fz;
    float c11 = v110 * gz + v111 * fz;
    float c0 = c00 * gy + c01 * fy;
    float c1 = c10 * gy + c11 * fy;
    return c0 * gx + c1 * fx;
}

__device__ __forceinline__ void slab_clip(float p0, float dd, float lo, float hi,
                                          float& t0, float& t1) {
    if (fabsf(dd) > 1e-9f) {
        float r = 1.0f / dd;
        float ta = (lo - p0) * r, tb = (hi - p0) * r;
        t0 = fmaxf(t0, fminf(ta, tb));
        t1 = fminf(t1, fmaxf(ta, tb));
    } else if (p0 <= lo || p0 >= hi) {
        t1 = -1e9f;
    }
}

// ---------------------------------------------------------------------------
// Kernel B: cone-beam forward projection
// block = (128 v-threads, 2 step-halves); grid = (u, view)
// ---------------------------------------------------------------------------
__global__ void __launch_bounds__(256, 6)
proj_kernel(const float* __restrict__ src_pos,
            const float* __restrict__ det_center,
            const float* __restrict__ det_u_vec,
            const float* __restrict__ det_v_vec,
            const float* __restrict__ pdu,
            const float* __restrict__ pdv,
            const float* __restrict__ psp,
            float* __restrict__ sino) {
    const int v = threadIdx.x;      // detector v (z axis): contiguous output + z locality
    const int ty = threadIdx.y;     // step-range half
    const int u = blockIdx.x;
    const int view = blockIdx.y;

    const float du = __ldg(pdu);
    const float dv = __ldg(pdv);
    const float inv_sp = 1.0f / __ldg(psp);

    const float sx = __ldg(&src_pos[view * 3 + 0]);
    const float sy = __ldg(&src_pos[view * 3 + 1]);
    const float sz = __ldg(&src_pos[view * 3 + 2]);
    const float ccx = __ldg(&det_center[view * 3 + 0]);
    const float ccy = __ldg(&det_center[view * 3 + 1]);
    const float ccz = __ldg(&det_center[view * 3 + 2]);
    const float ux = __ldg(&det_u_vec[view * 3 + 0]);
    const float uy = __ldg(&det_u_vec[view * 3 + 1]);
    const float uz = __ldg(&det_u_vec[view * 3 + 2]);
    const float vx = __ldg(&det_v_vec[view * 3 + 0]);
    const float vy = __ldg(&det_v_vec[view * 3 + 1]);
    const float vz = __ldg(&det_v_vec[view * 3 + 2]);

    const float uu = ((float)u - (float)(DETU - 1) * 0.5f) * du;
    const float vv = ((float)v - (float)(DETV - 1) * 0.5f) * dv;

    const float dx = (ccx + uu * ux + vv * vx) - sx;
    const float dy = (ccy + uu * uy + vv * vy) - sy;
    const float dz = (ccz + uu * uz + vv * vz) - sz;
    const float ray_len = sqrtf(dx * dx + dy * dy + dz * dz);

    // voxel-space parametric line: vox(s) = p0 + s * dd
    const float cx = (float)(NX - 1) * 0.5f;
    const float cy = (float)(NY - 1) * 0.5f;
    const float cz = (float)(NZ - 1) * 0.5f;
    const float p0x = fmaf(sx, inv_sp, cx);
    const float p0y = fmaf(sy, inv_sp, cy);
    const float p0z = fmaf(sz, inv_sp, cz);
    const float ddx = dx * inv_sp;
    const float ddy = dy * inv_sp;
    const float ddz = dz * inv_sp;

    // outer clip (anything beyond contributes exactly 0)
    float t0 = 0.0f, t1 = 1.0f;
    slab_clip(p0x, ddx, -1.0f, (float)NX, t0, t1);
    slab_clip(p0y, ddy, -1.0f, (float)NY, t0, t1);
    slab_clip(p0z, ddz, -1.0f, (float)NZ, t0, t1);

    int k0 = 0, k1 = -1;
    if (t1 > t0) {
        k0 = max((int)ceilf(t0 * (float)NSTEPS - 0.5f) - 1, 0);
        k1 = min((int)floorf(t1 * (float)NSTEPS - 0.5f) + 1, NSTEPS - 1);
    }

    // inner (interior) clip: all 8 taps in-bounds for px,py,pz in [0, N-1)
    float s0 = 0.0f, s1 = 1.0f;
    slab_clip(p0x, ddx, 1e-3f, (float)NX - 1.001f, s0, s1);
    slab_clip(p0y, ddy, 1e-3f, (float)NY - 1.001f, s0, s1);
    slab_clip(p0z, ddz, 1e-3f, (float)NZ - 1.001f, s0, s1);

    int ki0, ki1;
    if (s1 > s0) {
        ki0 = max((int)ceilf(s0 * (float)NSTEPS - 0.5f) + 1, k0);
        ki1 = min((int)floorf(s1 * (float)NSTEPS - 0.5f) - 1, k1);
    } else {
        ki0 = k1 + 1; ki1 = k1;   // empty fast range
    }
    if (ki1 < ki0) { ki0 = k1 + 1; ki1 = k1; }

    // per-step voxel deltas: vox(k) = base + k * ddn
    const float inv_n = 1.0f / (float)NSTEPS;
    const float ddnx = ddx * inv_n, ddny = ddy * inv_n, ddnz = ddz * inv_n;
    const float bx = fmaf(0.5f, ddnx, p0x);
    const float by = fmaf(0.5f, ddny, p0y);
    const float bz = fmaf(0.5f, ddnz, p0z);

    // split step range across the two y-threads
    const int n = max(k1 - k0 + 1, 0);
    const int half = n >> 1;
    int a, b;
    if (ty == 0) { a = k0;        b = k0 + half - 1; }
    else         { a = k0 + half; b = k1; }

    float acc = 0.0f;

    // leading boundary (masked)
    for (int k = a; k <= min(b, ki0 - 1); ++k) {
        float kf = (float)k;
        acc += trilin_masked(fmaf(kf, ddnx, bx), fmaf(kf, ddny, by), fmaf(kf, ddnz, bz));
    }
    // interior (fast, unpredicated)
#pragma unroll 4
    for (int k = max(a, ki0); k <= min(b, ki1); ++k) {
        float kf = (float)k;
        acc += trilin_fast(fmaf(kf, ddnx, bx), fmaf(kf, ddny, by), fmaf(kf, ddnz, bz));
    }
    // trailing boundary (masked)
    for (int k = max(a, ki1 + 1); k <= b; ++k) {
        float kf = (float)k;
        acc += trilin_masked(fmaf(kf, ddnx, bx), fmaf(kf, ddny, by), fmaf(kf, ddnz, bz));
    }

    __shared__ float part[DETV];
    if (ty == 1) part[v] = acc;
    __syncthreads();
    if (ty == 0) {
        sino[(view * DETU + u) * DETV + v] = (acc + part[v]) * (ray_len * inv_n);
    }
}

// ---------------------------------------------------------------------------
// Launch
// ---------------------------------------------------------------------------
extern "C" void kernel_launch(void* const* d_in, const int* in_sizes, int n_in,
                              void* d_out, int out_size) {
    const float* x    = (const float*)d_in[0];
    const float* reco = (const float*)d_in[1];
    const float* src  = (const float*)d_in[2];
    const float* dc   = (const float*)d_in[3];
    const float* duv  = (const float*)d_in[4];
    const float* dvv  = (const float*)d_in[5];
    const float* pdu  = (const float*)d_in[6];
    const float* pdv  = (const float*)d_in[7];
    const float* psp  = (const float*)d_in[8];

    float* out  = (float*)d_out;
    float* sino = out;                                   // [8,128,128]
    float* relu = out + NVIEWS * DETU * DETV;            // [256^3]

    const int n4 = (NX * NY * NZ) / 4;
    add_relu_kernel<<<n4 / 256, 256>>>(x, reco, relu);

    dim3 grid(DETU, NVIEWS);
    dim3 block(DETV, 2);
    proj_kernel<<<grid, block>>>(src, dc, duv, dvv, pdu, pdv, psp, sino);
}